// round 12
// baseline (speedup 1.0000x reference)
#include <cuda_runtime.h>
#include <cstdint>

// Problem constants
#define TV          16384           // T * V
#define CTX         16              // T
#define VOCABSZ     1024            // V
#define NB          256             // batch
#define GROUP       16              // consecutive W rows per output group
#define NGROUPS     (TV / GROUP)    // 1024 groups
#define NSM         148             // persistent CTAs (1 per SM)
#define HALF        (TV / 2)        // 8192 floats = 32 KB half-row chunk
#define NBUF        6               // pipeline depth (6 x 32KB = 192KB smem)
#define CHUNK_BYTES (HALF * 4)      // 32 KB

// out[b, j] = relu( bias[j] + sum_t W[j, x[b,t] + t*V] )
//
// HBM-bound streaming of W (1 GB, read exactly once). Persistent CTAs with
// CONTIGUOUS row ranges (sequential ~7MB stream per SM, best DRAM locality)
// and a 6-deep cp.async.bulk pipeline of 32KB half-row chunks: up to five
// copies (160KB) in flight per SM and 2x finer producer/consumer handoff
// than the 64KB-row version, covering the per-SM BW*latency product that
// capped prior versions at ~85% DRAM duty.
//
// t-structure: col[t] = x[b,t] + t*1024 lies in [t*1024,(t+1)*1024), so
// t=0..7 index the lower 32KB half of a row, t=8..15 the upper half.

extern __shared__ float s_buf[];   // NBUF * HALF floats = 192 KB dynamic smem

__device__ __forceinline__ uint32_t smem_u32(const void* p) {
    return (uint32_t)__cvta_generic_to_shared(p);
}

__device__ __forceinline__ void bulk_load_chunk(uint32_t dst_smem,
                                                const float* src,
                                                uint32_t mbar) {
    asm volatile(
        "mbarrier.arrive.expect_tx.shared::cta.b64 _, [%0], %1;"
        :: "r"(mbar), "r"((uint32_t)CHUNK_BYTES) : "memory");
    asm volatile(
        "cp.async.bulk.shared::cluster.global.mbarrier::complete_tx::bytes "
        "[%0], [%1], %2, [%3];"
        :: "r"(dst_smem), "l"(src), "r"((uint32_t)CHUNK_BYTES), "r"(mbar)
        : "memory");
}

__device__ __forceinline__ void mbar_wait(uint32_t mbar, uint32_t phase) {
    asm volatile(
        "{\n\t"
        ".reg .pred P;\n\t"
        "WAIT_%=: mbarrier.try_wait.parity.acquire.cta.shared::cta.b64 P, [%0], %1, 0x989680;\n\t"
        "@P bra DONE_%=;\n\t"
        "bra WAIT_%=;\n\t"
        "DONE_%=:\n\t"
        "}"
        :: "r"(mbar), "r"(phase) : "memory");
}

__global__ __launch_bounds__(256, 1)
void lr_persist2_kernel(const int*   __restrict__ x,
                        const float* __restrict__ W,
                        const float* __restrict__ bias,
                        float*       __restrict__ out)
{
    __shared__ alignas(8) uint64_t mbar[NBUF];
    const int tid = threadIdx.x;            // = batch index b
    const int bid = blockIdx.x;

    // Contiguous group range: CTA b owns cnt = 6 + (b < 136) groups starting
    // at start_g = 6*b + min(b, 136).  (1024 = 6*148 + 136)
    const int extra    = (bid < 136) ? bid : 136;
    const int start_g  = 6 * bid + extra;
    const int cnt_g    = 6 + (bid < 136 ? 1 : 0);
    const int start_row = start_g * GROUP;          // multiple of 16
    const int n_rows    = cnt_g * GROUP;            // 96 or 112
    const int n_chunks  = n_rows * 2;               // 192 or 224  (> NBUF)

    uint32_t mb[NBUF], sb[NBUF];
    #pragma unroll
    for (int i = 0; i < NBUF; i++) {
        mb[i] = smem_u32(&mbar[i]);
        sb[i] = smem_u32(s_buf + i * HALF);
    }

    if (tid == 0) {
        #pragma unroll
        for (int i = 0; i < NBUF; i++)
            asm volatile("mbarrier.init.shared::cta.b64 [%0], 1;"
                         :: "r"(mb[i]) : "memory");
        asm volatile("fence.proxy.async.shared::cta;" ::: "memory");
    }
    __syncthreads();

    const float* Wbase = W + (size_t)start_row * TV;

    // Prologue: launch the first NBUF half-row chunks (3 rows).
    if (tid == 0) {
        #pragma unroll
        for (int i = 0; i < NBUF; i++)
            bulk_load_chunk(sb[i],
                            Wbase + (size_t)(i >> 1) * TV + (i & 1) * HALF,
                            mb[i]);
    }

    // Chunk-local column indices (overlaps with prologue copies).
    // x is int32 on device (JAX default downcasts int64).
    //   lower chunk: cols_lo[t] = x[b,t] + t*1024            (t = 0..7)
    //   upper chunk: cols_hi[t] = x[b,8+t] + t*1024          (t = 0..7)
    int cols_lo[8], cols_hi[8];
    {
        const int4* xb = (const int4*)(x + tid * CTX);
        #pragma unroll
        for (int q = 0; q < 2; q++) {
            int4 v = xb[q];
            cols_lo[q * 4 + 0] = v.x + (q * 4 + 0) * VOCABSZ;
            cols_lo[q * 4 + 1] = v.y + (q * 4 + 1) * VOCABSZ;
            cols_lo[q * 4 + 2] = v.z + (q * 4 + 2) * VOCABSZ;
            cols_lo[q * 4 + 3] = v.w + (q * 4 + 3) * VOCABSZ;
        }
        #pragma unroll
        for (int q = 0; q < 2; q++) {
            int4 v = xb[2 + q];
            cols_hi[q * 4 + 0] = v.x + (q * 4 + 0) * VOCABSZ;
            cols_hi[q * 4 + 1] = v.y + (q * 4 + 1) * VOCABSZ;
            cols_hi[q * 4 + 2] = v.z + (q * 4 + 2) * VOCABSZ;
            cols_hi[q * 4 + 3] = v.w + (q * 4 + 3) * VOCABSZ;
        }
    }

    float acc[GROUP];
    int buf = 0, phase = 0;    // completion phase of buffer `buf`

    #pragma unroll 1
    for (int q = 0; q < n_chunks; q++) {
        mbar_wait(mb[buf], phase);

        const int row_local = q >> 1;
        const int r         = row_local & (GROUP - 1);
        const float* __restrict__ cp = s_buf + buf * HALF;

        float s = 0.f;
        if ((q & 1) == 0) {
            #pragma unroll
            for (int t = 0; t < 8; t++) s += cp[cols_lo[t]];
            acc[r] = s;
        } else {
            #pragma unroll
            for (int t = 0; t < 8; t++) s += cp[cols_hi[t]];
            acc[r] += s;
        }

        __syncthreads();    // everyone done reading this chunk

        // Keep the pipeline streaming (across rows and groups alike).
        if (q + NBUF < n_chunks && tid == 0) {
            const int qq = q + NBUF;
            bulk_load_chunk(sb[buf],
                            Wbase + (size_t)(qq >> 1) * TV + (qq & 1) * HALF,
                            mb[buf]);
        }

        if (++buf == NBUF) { buf = 0; phase ^= 1; }

        // Group complete (both halves of the 16th row done): epilogue
        // overlaps with in-flight copies.
        if ((q & 1) == 1 && r == GROUP - 1) {
            const int j0 = start_row + row_local - r;   // group base row
            size_t base = (size_t)tid * TV + j0;
            #pragma unroll
            for (int k = 0; k < GROUP; k += 4) {
                float4 bv = *(const float4*)(bias + j0 + k);
                float4 o;
                o.x = fmaxf(acc[k + 0] + bv.x, 0.f);
                o.y = fmaxf(acc[k + 1] + bv.y, 0.f);
                o.z = fmaxf(acc[k + 2] + bv.z, 0.f);
                o.w = fmaxf(acc[k + 3] + bv.w, 0.f);
                *(float4*)(out + base + k) = o;
            }
        }
    }
}

extern "C" void kernel_launch(void* const* d_in, const int* in_sizes, int n_in,
                              void* d_out, int out_size)
{
    // Identify inputs by element count:
    //   x: 256*16 = 4096 (int32), W: 16384*16384 (f32), b: 16384 (f32)
    const int*   x    = nullptr;
    const float* W    = nullptr;
    const float* bias = nullptr;
    for (int i = 0; i < n_in; i++) {
        if (in_sizes[i] == NB * CTX)          x    = (const int*)d_in[i];
        else if (in_sizes[i] == TV)           bias = (const float*)d_in[i];
        else                                  W    = (const float*)d_in[i];
    }
    float* out = (float*)d_out;

    cudaFuncSetAttribute(lr_persist2_kernel,
                         cudaFuncAttributeMaxDynamicSharedMemorySize,
                         NBUF * HALF * sizeof(float));

    dim3 grid(NSM);     // persistent: one CTA per SM
    dim3 block(256);
    lr_persist2_kernel<<<grid, block, NBUF * HALF * sizeof(float)>>>(x, W, bias, out);
}

// round 13
// speedup vs baseline: 1.0082x; 1.0082x over previous
#include <cuda_runtime.h>
#include <cstdint>

// Problem constants
#define TV      16384   // T * V
#define CTX     16      // T
#define VOCABSZ 1024    // V
#define NB      256     // batch
#define ROWS    8       // W rows per CTA (main kernel)
#define KSLOT   16      // 4096 / 256 staging slots per thread

// out[b, j] = relu( bias[j] + sum_t W[j, x[b,t] + t*V] )
//
// Traffic-compaction design: only ~3620 of the 16384 columns of W are ever
// indexed (union over b,t of x[b,t]+t*V). A prep kernel computes the sorted
// unique column list U and the rank map m[b][t]; the main kernel gathers
// only those columns per row with sorted __ldcg loads (DRAM fetches only
// touched 32B sectors: ~86.5% of bytes), staging them in smem, then each
// thread (=batch) accumulates its 16 picks via the rank map.

__device__ int d_nu;                        // number of unique columns
__device__ __align__(16) int d_U[TV / 4];   // unique sorted columns (<=4096)
__device__ __align__(16) int d_m[NB * CTX]; // rank of col[b,t] in U

// ---------------------------------------------------------------- prep ----
__global__ void lr_prep_kernel(const int* __restrict__ x)
{
    __shared__ uint32_t bm[512];     // 16384-bit column bitmap
    __shared__ int      base_s[512]; // exclusive prefix of popcounts
    __shared__ int      s_nu;

    const int tid = threadIdx.x;     // 256 threads

    bm[tid] = 0; bm[tid + 256] = 0;
    __syncthreads();

    // Mark all referenced columns.
    for (int i = tid; i < NB * CTX; i += 256) {
        int t   = i & (CTX - 1);
        int col = x[i] + t * VOCABSZ;
        atomicOr(&bm[col >> 5], 1u << (col & 31));
    }
    __syncthreads();

    // Warp 0: serial-per-lane + warp scan over 512 word popcounts.
    if (tid < 32) {
        int loc[16], tot = 0;
        #pragma unroll
        for (int k = 0; k < 16; k++) {
            loc[k] = tot;
            tot += __popc(bm[tid * 16 + k]);
        }
        int v = tot;
        #pragma unroll
        for (int off = 1; off < 32; off <<= 1) {
            int n = __shfl_up_sync(0xffffffffu, v, off);
            if (tid >= off) v += n;
        }
        int ebase = v - tot;   // exclusive base for this lane's 16 words
        #pragma unroll
        for (int k = 0; k < 16; k++)
            base_s[tid * 16 + k] = ebase + loc[k];
        if (tid == 31) s_nu = v;
    }
    __syncthreads();

    // Emit unique sorted column list U.
    for (int w = tid; w < 512; w += 256) {
        uint32_t bits = bm[w];
        int idx = base_s[w];
        while (bits) {
            int b = __ffs(bits) - 1;
            d_U[idx++] = w * 32 + b;
            bits &= bits - 1;
        }
    }
    // Pad the tail so the main kernel can load unconditionally.
    for (int i = s_nu + tid; i < TV / 4; i += 256)
        d_U[i] = 0;

    // Rank map m[b*CTX + t].
    for (int i = tid; i < NB * CTX; i += 256) {
        int t   = i & (CTX - 1);
        int col = x[i] + t * VOCABSZ;
        int w   = col >> 5;
        d_m[i]  = base_s[w] + __popc(bm[w] & ((1u << (col & 31)) - 1u));
    }

    if (tid == 0) d_nu = s_nu;
}

// ---------------------------------------------------------------- main ----
__global__ __launch_bounds__(256, 3)
void lr_compact_kernel(const float* __restrict__ W,
                       const float* __restrict__ bias,
                       float*       __restrict__ out)
{
    __shared__ float s_g[TV / 4];    // staged gathered values (16 KB)

    const int tid = threadIdx.x;     // = batch index b
    const int j0  = blockIdx.x * ROWS;

    // Staging slots owned by this thread (same columns every row).
    int u_idx[KSLOT];
    #pragma unroll
    for (int k = 0; k < KSLOT; k++)
        u_idx[k] = d_U[tid + 256 * k];    // padded with 0 beyond n_u

    // Rank map for this batch.
    int m[CTX];
    {
        const int4* mp = (const int4*)(d_m + tid * CTX);
        #pragma unroll
        for (int q = 0; q < CTX / 4; q++) {
            int4 v = mp[q];
            m[q * 4 + 0] = v.x; m[q * 4 + 1] = v.y;
            m[q * 4 + 2] = v.z; m[q * 4 + 3] = v.w;
        }
    }

    // Prefetch row 0 gathers into registers (sorted cols -> near-streaming,
    // sector-granular DRAM fetches; L2-only to avoid L1 pollution).
    float pf[KSLOT];
    {
        const float* rowp = W + (size_t)j0 * TV;
        #pragma unroll
        for (int k = 0; k < KSLOT; k++)
            pf[k] = __ldcg(rowp + u_idx[k]);
    }

    float acc[ROWS];

    #pragma unroll 1
    for (int r = 0; r < ROWS; r++) {
        // Publish prefetched row r.
        #pragma unroll
        for (int k = 0; k < KSLOT; k++)
            s_g[tid + 256 * k] = pf[k];
        __syncthreads();

        // Issue next row's gathers; latency overlaps the smem accumulate.
        if (r + 1 < ROWS) {
            const float* rowp = W + (size_t)(j0 + r + 1) * TV;
            #pragma unroll
            for (int k = 0; k < KSLOT; k++)
                pf[k] = __ldcg(rowp + u_idx[k]);
        }

        // Accumulate this thread's 16 picks.
        float s = 0.f;
        #pragma unroll
        for (int t = 0; t < CTX; t++)
            s += s_g[m[t]];
        acc[r] = s;

        __syncthreads();   // all reads done before s_g is overwritten
    }

    // Epilogue: bias + relu, 2x float4 stores (sector-dense).
    size_t base = (size_t)tid * TV + j0;
    #pragma unroll
    for (int r = 0; r < ROWS; r += 4) {
        float4 bv = *(const float4*)(bias + j0 + r);
        float4 o;
        o.x = fmaxf(acc[r + 0] + bv.x, 0.f);
        o.y = fmaxf(acc[r + 1] + bv.y, 0.f);
        o.z = fmaxf(acc[r + 2] + bv.z, 0.f);
        o.w = fmaxf(acc[r + 3] + bv.w, 0.f);
        *(float4*)(out + base + r) = o;
    }
}

extern "C" void kernel_launch(void* const* d_in, const int* in_sizes, int n_in,
                              void* d_out, int out_size)
{
    // Identify inputs by element count:
    //   x: 256*16 = 4096 (int32), W: 16384*16384 (f32), b: 16384 (f32)
    const int*   x    = nullptr;
    const float* W    = nullptr;
    const float* bias = nullptr;
    for (int i = 0; i < n_in; i++) {
        if (in_sizes[i] == NB * CTX)          x    = (const int*)d_in[i];
        else if (in_sizes[i] == TV)           bias = (const float*)d_in[i];
        else                                  W    = (const float*)d_in[i];
    }
    float* out = (float*)d_out;

    lr_prep_kernel<<<1, 256>>>(x);
    lr_compact_kernel<<<TV / ROWS, 256>>>(W, bias, out);   // 2048 CTAs
}

// round 14
// speedup vs baseline: 1.0176x; 1.0094x over previous
#include <cuda_runtime.h>
#include <cstdint>

// Problem constants
#define TV      16384   // T * V
#define CTX     16      // T
#define VOCABSZ 1024    // V
#define NB      256     // batch
#define ROWS    8       // W rows per CTA
#define KSLOT   16      // 4096 / 256 staging slots per thread

// out[b, j] = relu( bias[j] + sum_t W[j, x[b,t] + t*V] )
//
// Fused compaction kernel. Only ~3620 of 16384 columns of W are ever
// indexed; each CTA (redundantly, ~0.7us) builds the sorted unique column
// list U and per-batch rank map in smem, then gathers only those columns
// per row with sorted __ldcg loads + register prefetch pipeline. Fusing
// removes the 12.4us separate-prep-kernel overhead measured in R13 while
// keeping the 159.7us main-loop structure (DRAM 86.6%, at the byte floor:
// effective DRAM granularity is 64B so traffic is ~irreducible at ~1.1GB).

__global__ __launch_bounds__(256, 3)
void lr_fused_kernel(const int*   __restrict__ x,
                     const float* __restrict__ W,
                     const float* __restrict__ bias,
                     float*       __restrict__ out)
{
    __shared__ uint32_t bm[512];      // 16384-bit column bitmap   (2 KB)
    __shared__ int      base_s[512];  // exclusive popcount prefix (2 KB)
    __shared__ int      s_U[TV / 4];  // unique sorted columns     (16 KB)
    __shared__ float    s_g[TV / 4];  // staged gathered values    (16 KB)
    __shared__ int      s_nu;

    const int tid = threadIdx.x;      // = batch index b
    const int j0  = blockIdx.x * ROWS;

    // ---------- prep (redundant per CTA, ~1200 cyc) ----------
    bm[tid] = 0; bm[tid + 256] = 0;
    __syncthreads();

    // This thread's 16 columns (x is int32 on device; JAX downcasts int64).
    int cols[CTX];
    {
        const int4* xb = (const int4*)(x + tid * CTX);
        #pragma unroll
        for (int q = 0; q < CTX / 4; q++) {
            int4 v = xb[q];
            cols[q * 4 + 0] = v.x + (q * 4 + 0) * VOCABSZ;
            cols[q * 4 + 1] = v.y + (q * 4 + 1) * VOCABSZ;
            cols[q * 4 + 2] = v.z + (q * 4 + 2) * VOCABSZ;
            cols[q * 4 + 3] = v.w + (q * 4 + 3) * VOCABSZ;
        }
    }
    #pragma unroll
    for (int t = 0; t < CTX; t++)
        atomicOr(&bm[cols[t] >> 5], 1u << (cols[t] & 31));
    __syncthreads();

    // Warp 0: serial-per-lane + warp scan over 512 word popcounts.
    if (tid < 32) {
        int loc[16], tot = 0;
        #pragma unroll
        for (int k = 0; k < 16; k++) {
            loc[k] = tot;
            tot += __popc(bm[tid * 16 + k]);
        }
        int v = tot;
        #pragma unroll
        for (int off = 1; off < 32; off <<= 1) {
            int n = __shfl_up_sync(0xffffffffu, v, off);
            if (tid >= off) v += n;
        }
        int ebase = v - tot;
        #pragma unroll
        for (int k = 0; k < 16; k++)
            base_s[tid * 16 + k] = ebase + loc[k];
        if (tid == 31) s_nu = v;
    }
    __syncthreads();

    // Emit unique sorted column list into smem.
    #pragma unroll
    for (int w = tid; w < 512; w += 256) {
        uint32_t bits = bm[w];
        int idx = base_s[w];
        while (bits) {
            int b = __ffs(bits) - 1;
            s_U[idx++] = w * 32 + b;
            bits &= bits - 1;
        }
    }
    // Pad tail so slot loads are unconditional (duplicates of col 0: L1-hit).
    for (int i = s_nu + tid; i < TV / 4; i += 256)
        s_U[i] = 0;

    // Rank of each of this thread's columns.
    int m[CTX];
    #pragma unroll
    for (int t = 0; t < CTX; t++) {
        int w = cols[t] >> 5;
        m[t] = base_s[w] + __popc(bm[w] & ((1u << (cols[t] & 31)) - 1u));
    }
    __syncthreads();

    // Staging slots owned by this thread (same columns every row).
    int u_idx[KSLOT];
    #pragma unroll
    for (int k = 0; k < KSLOT; k++)
        u_idx[k] = s_U[tid + 256 * k];

    // ---------- main row pipeline (identical to R13 structure) ----------
    // Prefetch row 0 gathers into registers (sorted cols -> ~5 lines/warp,
    // L2-only to avoid L1 pollution).
    float pf[KSLOT];
    {
        const float* rowp = W + (size_t)j0 * TV;
        #pragma unroll
        for (int k = 0; k < KSLOT; k++)
            pf[k] = __ldcg(rowp + u_idx[k]);
    }

    float acc[ROWS];

    #pragma unroll 1
    for (int r = 0; r < ROWS; r++) {
        // Publish prefetched row r.
        #pragma unroll
        for (int k = 0; k < KSLOT; k++)
            s_g[tid + 256 * k] = pf[k];
        __syncthreads();

        // Issue next row's gathers; latency overlaps the smem accumulate.
        if (r + 1 < ROWS) {
            const float* rowp = W + (size_t)(j0 + r + 1) * TV;
            #pragma unroll
            for (int k = 0; k < KSLOT; k++)
                pf[k] = __ldcg(rowp + u_idx[k]);
        }

        // Accumulate this thread's 16 picks.
        float s = 0.f;
        #pragma unroll
        for (int t = 0; t < CTX; t++)
            s += s_g[m[t]];
        acc[r] = s;

        __syncthreads();   // all reads done before s_g is overwritten
    }

    // Epilogue: bias + relu, 2x float4 stores (sector-dense).
    size_t base = (size_t)tid * TV + j0;
    #pragma unroll
    for (int r = 0; r < ROWS; r += 4) {
        float4 bv = *(const float4*)(bias + j0 + r);
        float4 o;
        o.x = fmaxf(acc[r + 0] + bv.x, 0.f);
        o.y = fmaxf(acc[r + 1] + bv.y, 0.f);
        o.z = fmaxf(acc[r + 2] + bv.z, 0.f);
        o.w = fmaxf(acc[r + 3] + bv.w, 0.f);
        *(float4*)(out + base + r) = o;
    }
}

extern "C" void kernel_launch(void* const* d_in, const int* in_sizes, int n_in,
                              void* d_out, int out_size)
{
    // Identify inputs by element count:
    //   x: 256*16 = 4096 (int32), W: 16384*16384 (f32), b: 16384 (f32)
    const int*   x    = nullptr;
    const float* W    = nullptr;
    const float* bias = nullptr;
    for (int i = 0; i < n_in; i++) {
        if (in_sizes[i] == NB * CTX)          x    = (const int*)d_in[i];
        else if (in_sizes[i] == TV)           bias = (const float*)d_in[i];
        else                                  W    = (const float*)d_in[i];
    }
    float* out = (float*)d_out;

    lr_fused_kernel<<<TV / ROWS, 256>>>(x, W, bias, out);   // 2048 CTAs
}